// round 2
// baseline (speedup 1.0000x reference)
#include <cuda_runtime.h>

#define NB   32
#define CIN  64
#define COUT 128
#define HW   4096            // 64*64 spatial per (n,ci)
#define INV_OHW (1.0f/4489.0f)  // 1/(67*67)
#define GRID (NB*CIN + CIN)  // 2048 x-reduce blocks + 64 w-reduce blocks

__device__ float g_Sx[NB * CIN];
__device__ float g_Sw[CIN * COUT];
__device__ unsigned int g_count = 0;

__device__ __forceinline__ float warp_sum(float v) {
    v += __shfl_xor_sync(0xffffffffu, v, 16);
    v += __shfl_xor_sync(0xffffffffu, v, 8);
    v += __shfl_xor_sync(0xffffffffu, v, 4);
    v += __shfl_xor_sync(0xffffffffu, v, 2);
    v += __shfl_xor_sync(0xffffffffu, v, 1);
    return v;
}
__device__ __forceinline__ float warp_max(float v) {
    v = fmaxf(v, __shfl_xor_sync(0xffffffffu, v, 16));
    v = fmaxf(v, __shfl_xor_sync(0xffffffffu, v, 8));
    v = fmaxf(v, __shfl_xor_sync(0xffffffffu, v, 4));
    v = fmaxf(v, __shfl_xor_sync(0xffffffffu, v, 2));
    v = fmaxf(v, __shfl_xor_sync(0xffffffffu, v, 1));
    return v;
}

__global__ void __launch_bounds__(256) fused_kernel(
    const float* __restrict__ x,
    const float* __restrict__ w,
    const float* __restrict__ cb,
    const float* __restrict__ eb,
    float* __restrict__ out)
{
    // 40KB shared, multi-purpose:
    //   reduce phase: first 8 floats = cross-warp scratch
    //   finalize phase 1: [0,8192) = Sw, [8192,10240) = SxT (ci-major, [ci][n])
    //   finalize phase 2: [0,4096) = pooled[n][co]
    __shared__ float sbuf[10240];
    __shared__ unsigned int s_arrived;

    const int b = blockIdx.x;
    const int t = threadIdx.x;
    const int lane = t & 31;
    const int wid  = t >> 5;

    // ---------------- reduce phase ----------------
    if (b < NB * CIN) {
        // Sx[b] = sum of 4096 contiguous floats
        const float4* p = reinterpret_cast<const float4*>(x) + (size_t)b * (HW / 4);
        float s = 0.0f;
        #pragma unroll
        for (int i = 0; i < 4; i++) {
            float4 v = p[t + i * 256];
            s += (v.x + v.y) + (v.z + v.w);
        }
        s = warp_sum(s);
        if (lane == 0) sbuf[wid] = s;
        __syncthreads();
        if (wid == 0) {
            float u = (lane < 8) ? sbuf[lane] : 0.0f;
            u += __shfl_xor_sync(0xffffffffu, u, 4);
            u += __shfl_xor_sync(0xffffffffu, u, 2);
            u += __shfl_xor_sync(0xffffffffu, u, 1);
            if (lane == 0) g_Sx[b] = u;
        }
    } else {
        // Sw[ci][co] = sum of the 16 contiguous kernel taps
        const int ci = b - NB * CIN;
        if (t < COUT) {
            const float4* p = reinterpret_cast<const float4*>(w)
                            + ((size_t)ci * COUT + t) * 4;
            float4 a0 = p[0], a1 = p[1], a2 = p[2], a3 = p[3];
            g_Sw[ci * COUT + t] =
                ((a0.x + a0.y) + (a0.z + a0.w)) +
                ((a1.x + a1.y) + (a1.z + a1.w)) +
                ((a2.x + a2.y) + (a2.z + a2.w)) +
                ((a3.x + a3.y) + (a3.z + a3.w));
        }
    }

    // ---------------- arrival ----------------
    __threadfence();
    __syncthreads();   // also guards sbuf reuse below
    if (t == 0) s_arrived = atomicAdd(&g_count, 1u);
    __syncthreads();
    if (s_arrived != GRID - 1) return;
    if (t == 0) g_count = 0;   // reset for next graph replay

    // ---------------- finalize (last block only) ----------------
    float* sh_sw  = sbuf;          // [ci*COUT + co], 8192 floats
    float* sh_sxT = sbuf + 8192;   // [ci*NB + n],    2048 floats

    for (int i = t; i < CIN * COUT; i += 256) sh_sw[i] = g_Sw[i];
    for (int i = t; i < NB * CIN;   i += 256) {
        int n = i >> 6, ci = i & 63;
        sh_sxT[ci * NB + n] = g_Sx[i];
    }
    __syncthreads();

    const int co   = t & 127;
    const int n0   = (t >> 7) * 16;   // this thread owns n in [n0, n0+16)

    float acc[16];
    #pragma unroll
    for (int j = 0; j < 16; j++) acc[j] = 0.0f;

    #pragma unroll 4
    for (int ci = 0; ci < CIN; ci++) {
        float swv = sh_sw[ci * COUT + co];
        const float4* sxp = reinterpret_cast<const float4*>(&sh_sxT[ci * NB + n0]);
        float4 a = sxp[0], b4 = sxp[1], c = sxp[2], d = sxp[3];
        acc[0]  = fmaf(a.x,  swv, acc[0]);
        acc[1]  = fmaf(a.y,  swv, acc[1]);
        acc[2]  = fmaf(a.z,  swv, acc[2]);
        acc[3]  = fmaf(a.w,  swv, acc[3]);
        acc[4]  = fmaf(b4.x, swv, acc[4]);
        acc[5]  = fmaf(b4.y, swv, acc[5]);
        acc[6]  = fmaf(b4.z, swv, acc[6]);
        acc[7]  = fmaf(b4.w, swv, acc[7]);
        acc[8]  = fmaf(c.x,  swv, acc[8]);
        acc[9]  = fmaf(c.y,  swv, acc[9]);
        acc[10] = fmaf(c.z,  swv, acc[10]);
        acc[11] = fmaf(c.w,  swv, acc[11]);
        acc[12] = fmaf(d.x,  swv, acc[12]);
        acc[13] = fmaf(d.y,  swv, acc[13]);
        acc[14] = fmaf(d.z,  swv, acc[14]);
        acc[15] = fmaf(d.w,  swv, acc[15]);
    }

    const float bias = cb[co] + eb[co];

    __syncthreads();   // everyone done reading sh_sw before aliasing it
    float* sh_pooled = sbuf;   // [n*COUT + co], 4096 floats
    #pragma unroll
    for (int j = 0; j < 16; j++)
        sh_pooled[(n0 + j) * COUT + co] = acc[j] * INV_OHW + bias;
    __syncthreads();

    // LSE: warp `wid` handles batch rows [wid*4, wid*4+4)
    #pragma unroll
    for (int k = 0; k < 4; k++) {
        const int n = wid * 4 + k;
        float v0 = sh_pooled[n * COUT + lane];
        float v1 = sh_pooled[n * COUT + lane + 32];
        float v2 = sh_pooled[n * COUT + lane + 64];
        float v3 = sh_pooled[n * COUT + lane + 96];
        float m = fmaxf(fmaxf(v0, v1), fmaxf(v2, v3));
        m = warp_max(m);
        float e = __expf(v0 - m) + __expf(v1 - m) + __expf(v2 - m) + __expf(v3 - m);
        e = warp_sum(e);
        if (lane == 0) out[n] = 10.0f * (m + logf(e));
    }
}

extern "C" void kernel_launch(void* const* d_in, const int* in_sizes, int n_in,
                              void* d_out, int out_size) {
    const float* x  = (const float*)d_in[0];   // (32,64,64,64)
    const float* w  = (const float*)d_in[1];   // (64,128,4,4)
    const float* cb = (const float*)d_in[2];   // (128,)
    const float* eb = (const float*)d_in[3];   // (128,)
    float* out = (float*)d_out;                // (32,1)

    fused_kernel<<<GRID, 256>>>(x, w, cb, eb, out);
}

// round 3
// speedup vs baseline: 1.5805x; 1.5805x over previous
#include <cuda_runtime.h>

#define NB   32
#define CIN  64
#define COUT 128
#define HW   4096               // 64*64 spatial per (n,ci)
#define INV_OHW (1.0f/4489.0f)  // 1/(67*67)

// pooled[n][co] accumulated via float atomics; zero-init, re-zeroed by kernel 2
__device__ float g_pooled[NB * COUT];   // = {0} implicit static zero-init

__device__ __forceinline__ float warp_sum(float v) {
    v += __shfl_xor_sync(0xffffffffu, v, 16);
    v += __shfl_xor_sync(0xffffffffu, v, 8);
    v += __shfl_xor_sync(0xffffffffu, v, 4);
    v += __shfl_xor_sync(0xffffffffu, v, 2);
    v += __shfl_xor_sync(0xffffffffu, v, 1);
    return v;
}
__device__ __forceinline__ float warp_max(float v) {
    v = fmaxf(v, __shfl_xor_sync(0xffffffffu, v, 16));
    v = fmaxf(v, __shfl_xor_sync(0xffffffffu, v, 8));
    v = fmaxf(v, __shfl_xor_sync(0xffffffffu, v, 4));
    v = fmaxf(v, __shfl_xor_sync(0xffffffffu, v, 2));
    v = fmaxf(v, __shfl_xor_sync(0xffffffffu, v, 1));
    return v;
}

// Kernel 1: one block per (n,ci). Reduce 4096 x-floats -> s.
// Thread co sums its 16 weight taps -> sw, then RED.F32 s*sw into pooled[n][co].
__global__ void __launch_bounds__(256) reduce_acc_kernel(
    const float* __restrict__ x,
    const float* __restrict__ w)
{
    const int b  = blockIdx.x;          // b = n*CIN + ci
    const int ci = b & (CIN - 1);
    const int n  = b >> 6;
    const int t    = threadIdx.x;
    const int lane = t & 31;
    const int wid  = t >> 5;

    // Issue weight loads first (L2-hot across the 32 blocks sharing ci);
    // they overlap the DRAM-bound x reads below.
    float sw = 0.0f;
    if (t < COUT) {
        const float4* wp = reinterpret_cast<const float4*>(w)
                         + ((size_t)ci * COUT + t) * 4;   // 16 taps = 4 float4
        float4 a0 = wp[0], a1 = wp[1], a2 = wp[2], a3 = wp[3];
        sw = ((a0.x + a0.y) + (a0.z + a0.w))
           + ((a1.x + a1.y) + (a1.z + a1.w))
           + ((a2.x + a2.y) + (a2.z + a2.w))
           + ((a3.x + a3.y) + (a3.z + a3.w));
    }

    // x reduction: 256 threads x 4 float4 = 4096 floats
    const float4* p = reinterpret_cast<const float4*>(x) + (size_t)b * (HW / 4);
    float s = 0.0f;
    #pragma unroll
    for (int i = 0; i < 4; i++) {
        float4 v = p[t + i * 256];
        s += (v.x + v.y) + (v.z + v.w);
    }
    s = warp_sum(s);

    __shared__ float sh[8];
    __shared__ float sh_s;
    if (lane == 0) sh[wid] = s;
    __syncthreads();
    if (t == 0) {
        float u = sh[0] + sh[1] + sh[2] + sh[3]
                + sh[4] + sh[5] + sh[6] + sh[7];
        sh_s = u;
    }
    __syncthreads();

    if (t < COUT) {
        atomicAdd(&g_pooled[n * COUT + t], sh_s * sw);
    }
}

// Kernel 2: single block, 32 warps. Warp n: bias + LSE over pooled[n][:128],
// write out[n], then re-zero pooled row for the next graph replay.
__global__ void __launch_bounds__(1024) lse_kernel(
    const float* __restrict__ cb,
    const float* __restrict__ eb,
    float* __restrict__ out)
{
    const int n    = threadIdx.x >> 5;   // warp id = batch row
    const int lane = threadIdx.x & 31;

    float4* rowp = reinterpret_cast<float4*>(&g_pooled[n * COUT]) + lane;
    float4 v = *rowp;
    const float4 cb4 = reinterpret_cast<const float4*>(cb)[lane];
    const float4 eb4 = reinterpret_cast<const float4*>(eb)[lane];

    float p0 = v.x * INV_OHW + cb4.x + eb4.x;
    float p1 = v.y * INV_OHW + cb4.y + eb4.y;
    float p2 = v.z * INV_OHW + cb4.z + eb4.z;
    float p3 = v.w * INV_OHW + cb4.w + eb4.w;

    // re-zero for next replay (this lane owns these 4 entries)
    *rowp = make_float4(0.0f, 0.0f, 0.0f, 0.0f);

    float m = fmaxf(fmaxf(p0, p1), fmaxf(p2, p3));
    m = warp_max(m);
    float e = __expf(p0 - m) + __expf(p1 - m) + __expf(p2 - m) + __expf(p3 - m);
    e = warp_sum(e);
    if (lane == 0) out[n] = 10.0f * (m + logf(e));
}

extern "C" void kernel_launch(void* const* d_in, const int* in_sizes, int n_in,
                              void* d_out, int out_size) {
    const float* x  = (const float*)d_in[0];   // (32,64,64,64)
    const float* w  = (const float*)d_in[1];   // (64,128,4,4)
    const float* cb = (const float*)d_in[2];   // (128,)
    const float* eb = (const float*)d_in[3];   // (128,)
    float* out = (float*)d_out;                // (32,1)

    reduce_acc_kernel<<<NB * CIN, 256>>>(x, w);
    lse_kernel<<<1, 1024>>>(cb, eb, out);
}

// round 4
// speedup vs baseline: 1.7881x; 1.1313x over previous
#include <cuda_runtime.h>

#define NB   32
#define CIN  64
#define COUT 128
#define HW   4096               // 64*64 spatial per (n,ci)
#define INV_OHW (1.0f/4489.0f)  // 1/(67*67)

__device__ float g_Sx[NB * CIN];      // 2048
__device__ float g_Sw[CIN * COUT];    // 8192

__device__ __forceinline__ float warp_sum(float v) {
    v += __shfl_xor_sync(0xffffffffu, v, 16);
    v += __shfl_xor_sync(0xffffffffu, v, 8);
    v += __shfl_xor_sync(0xffffffffu, v, 4);
    v += __shfl_xor_sync(0xffffffffu, v, 2);
    v += __shfl_xor_sync(0xffffffffu, v, 1);
    return v;
}
__device__ __forceinline__ float warp_max(float v) {
    v = fmaxf(v, __shfl_xor_sync(0xffffffffu, v, 16));
    v = fmaxf(v, __shfl_xor_sync(0xffffffffu, v, 8));
    v = fmaxf(v, __shfl_xor_sync(0xffffffffu, v, 4));
    v = fmaxf(v, __shfl_xor_sync(0xffffffffu, v, 2));
    v = fmaxf(v, __shfl_xor_sync(0xffffffffu, v, 1));
    return v;
}

// ---------------- Kernel 1: reductions (R1 shape — near HBM floor) ----------
// blocks [0, 2048): Sx[n*CIN+ci] = sum over 4096 spatial floats
// blocks [2048, 2112): Sw[ci][co] = sum over 16 kernel taps
__global__ void __launch_bounds__(256) reduce_kernel(
    const float* __restrict__ x,
    const float* __restrict__ w)
{
    const int b = blockIdx.x;
    const int t = threadIdx.x;
    if (b < NB * CIN) {
        const float4* p = reinterpret_cast<const float4*>(x) + (size_t)b * (HW / 4);
        float s = 0.0f;
        #pragma unroll
        for (int i = 0; i < 4; i++) {
            float4 v = p[t + i * 256];
            s += (v.x + v.y) + (v.z + v.w);
        }
        s = warp_sum(s);
        __shared__ float sh[8];
        const int lane = t & 31;
        const int wid  = t >> 5;
        if (lane == 0) sh[wid] = s;
        __syncthreads();
        if (wid == 0) {
            float u = (lane < 8) ? sh[lane] : 0.0f;
            u += __shfl_xor_sync(0xffffffffu, u, 4);
            u += __shfl_xor_sync(0xffffffffu, u, 2);
            u += __shfl_xor_sync(0xffffffffu, u, 1);
            if (lane == 0) g_Sx[b] = u;
        }
    } else {
        const int ci = b - NB * CIN;
        if (t < COUT) {
            const float4* p = reinterpret_cast<const float4*>(w)
                            + ((size_t)ci * COUT + t) * 4;
            float4 a0 = p[0], a1 = p[1], a2 = p[2], a3 = p[3];
            g_Sw[ci * COUT + t] =
                ((a0.x + a0.y) + (a0.z + a0.w)) +
                ((a1.x + a1.y) + (a1.z + a1.w)) +
                ((a2.x + a2.y) + (a2.z + a2.w)) +
                ((a3.x + a3.y) + (a3.z + a3.w));
        }
    }
}

// ---------------- Kernel 2: PDL finalize -----------------------------------
// Launched with programmatic stream serialization: ramps up and preloads the
// (cold-DRAM) biases WHILE kernel 1 runs, then grid-syncs and finishes on
// L2-hot data. One block per n, thread co owns one output channel.
__global__ void __launch_bounds__(COUT) finalize_kernel(
    const float* __restrict__ cb,
    const float* __restrict__ eb,
    float* __restrict__ out)
{
    const int n    = blockIdx.x;
    const int co   = threadIdx.x;
    const int lane = co & 31;
    const int wid  = co >> 5;

    // Independent prologue — overlaps kernel 1.
    const float bias = cb[co] + eb[co];

    // Wait for kernel 1 completion (implicit trigger ⇒ its writes visible).
    cudaGridDependencySynchronize();

    __shared__ float sx[CIN];
    if (co < CIN) sx[co] = g_Sx[n * CIN + co];
    __syncthreads();

    float acc = 0.0f;
    #pragma unroll
    for (int ci = 0; ci < CIN; ci++)
        acc = fmaf(sx[ci], g_Sw[ci * COUT + co], acc);

    const float pooled = acc * INV_OHW + bias;

    // block max over 128 (4 warps)
    __shared__ float red[4], red2[4];
    float m = warp_max(pooled);
    if (lane == 0) red[wid] = m;
    __syncthreads();
    const float m0 = fmaxf(fmaxf(red[0], red[1]), fmaxf(red[2], red[3]));

    float e = __expf(pooled - m0);
    e = warp_sum(e);
    if (lane == 0) red2[wid] = e;
    __syncthreads();
    if (co == 0) {
        float tot = (red2[0] + red2[1]) + (red2[2] + red2[3]);
        out[n] = 10.0f * (m0 + logf(tot));
    }
}

extern "C" void kernel_launch(void* const* d_in, const int* in_sizes, int n_in,
                              void* d_out, int out_size) {
    const float* x  = (const float*)d_in[0];   // (32,64,64,64)
    const float* w  = (const float*)d_in[1];   // (64,128,4,4)
    const float* cb = (const float*)d_in[2];   // (128,)
    const float* eb = (const float*)d_in[3];   // (128,)
    float* out = (float*)d_out;                // (32,1)

    reduce_kernel<<<NB * CIN + CIN, 256>>>(x, w);

    // Finalize with Programmatic Dependent Launch: overlap its launch ramp +
    // bias prologue with the reduction kernel.
    cudaLaunchConfig_t cfg = {};
    cfg.gridDim  = dim3(NB, 1, 1);
    cfg.blockDim = dim3(COUT, 1, 1);
    cfg.dynamicSmemBytes = 0;
    cfg.stream = 0;
    cudaLaunchAttribute attrs[1];
    attrs[0].id = cudaLaunchAttributeProgrammaticStreamSerialization;
    attrs[0].val.programmaticStreamSerializationAllowed = 1;
    cfg.attrs = attrs;
    cfg.numAttrs = 1;
    cudaLaunchKernelEx(&cfg, finalize_kernel, cb, eb, out);
}